// round 11
// baseline (speedup 1.0000x reference)
#include <cuda_runtime.h>
#include <cuda_fp16.h>

#define NN 100000
#define NNP 100032   // padded to 64-row tiles
#define NE 1600000
#define NG 128
#define HID 64
#define NB 98        // ceil(NN / 1024)
#define NTILES 3125  // NN / 32  (pre_hist tiles)
#define LTILES 1563  // ceil(NN / 64) (gemm tiles)

typedef unsigned long long u64;

#define FMA4(acc, wv, sv) { (acc).x += (sv) * (wv).x; (acc).y += (sv) * (wv).y; \
                            (acc).z += (sv) * (wv).z; (acc).w += (sv) * (wv).w; }

// packed fp32x2 FMA (Blackwell): d.lo += a.lo*b.lo; d.hi += a.hi*b.hi (IEEE fp32 each)
__device__ __forceinline__ void fma2(u64& d, u64 a, u64 b) {
    asm("fma.rn.f32x2 %0, %1, %2, %0;" : "+l"(d) : "l"(a), "l"(b));
}
__device__ __forceinline__ float unpk_add(u64 v) {
    float lo, hi;
    asm("mov.b64 {%0, %1}, %2;" : "=f"(lo), "=f"(hi) : "l"(v));
    return lo + hi;
}

// ---------------- scratch (device globals: allocation-free) ----------------
// accumulated-into buffers (g_deg, g_pool, g_cnt, g_lb) are zeroed at the END
// of each kernel_launch (k_zero_post). Module-load zero-init covers call 1.
__device__ int    g_deg[NN];
__device__ int    g_rowptr[NN + 1];
__device__ int    g_cursor[NN];
__device__ int    g_col[NE];
__device__ unsigned long long g_lb[NB];  // lookback scan state (flag<<62 | value)
__device__ __half g_y[NNP * HID];        // y = h@W1, fp16 (gathered operand)
__device__ float  g_t[NNP * HID];        // t = relu(y_self+agg+b1), fp32
__device__ float  g_pool[NG * 4 * HID];  // pooled per-layer h', [G][256]
__device__ int    g_cnt[NG];
__device__ float  g_pooledT[HID * NG];   // JK output, transposed [c][g]

// convert float4 -> 4 packed halfs (uint2)
__device__ __forceinline__ uint2 f4_to_h4(float4 a) {
    __half2 lo = __floats2half2_rn(a.x, a.y);
    __half2 hi = __floats2half2_rn(a.z, a.w);
    uint2 r;
    r.x = *(unsigned*)&lo;
    r.y = *(unsigned*)&hi;
    return r;
}
// accumulate 8 packed halfs (uint4) into float acc[8]
__device__ __forceinline__ void add8h(float* a, uint4 v) {
    float2 f;
    f = __half22float2(*(__half2*)&v.x); a[0] += f.x; a[1] += f.y;
    f = __half22float2(*(__half2*)&v.y); a[2] += f.x; a[3] += f.y;
    f = __half22float2(*(__half2*)&v.z); a[4] += f.x; a[5] += f.y;
    f = __half22float2(*(__half2*)&v.w); a[6] += f.x; a[7] += f.y;
}

// ---------------- launch 0: fused y0 = x @ W1f (fp16 out) + histograms ----------------
__global__ __launch_bounds__(256) void k_pre_hist(const float* __restrict__ x,
                                                  const float* __restrict__ W1f,
                                                  const int* __restrict__ ei,
                                                  const int* __restrict__ batch,
                                                  __half* __restrict__ y0,
                                                  float* __restrict__ t0) {
    extern __shared__ float sm[];
    float* W1s = sm;          // 128*64 = 8192
    float* xs  = sm + 8192;   // 32*132
    int tid = threadIdx.x;
    for (int i = tid; i < 8192; i += 256) W1s[i] = W1f[i];
    // zero the pad rows (NN..NNP-1) of y (half) and t (float), once per call
    if (blockIdx.x == 0) {
        unsigned* yz = (unsigned*)(y0 + NN * 64);     // 2048 halfs = 1024 u32
        for (int i = tid; i < (NNP - NN) * 32; i += 256) yz[i] = 0u;
        for (int i = tid; i < (NNP - NN) * 64; i += 256) t0[NN * 64 + i] = 0.0f;
    }
    const int ty = tid >> 4, tx = tid & 15;
    const int m0 = ty * 2, c0 = tx * 4;
    const float4* __restrict__ x4 = (const float4*)x;

    for (int tile = blockIdx.x; tile < NTILES; tile += gridDim.x) {
        __syncthreads();
        // --- degree histogram: 512 edges per tile (3125*512 = NE exactly) ---
        {
            int e0 = tile * 512;
            int d0 = ei[NE + e0 + tid];
            int d1 = ei[NE + e0 + 256 + tid];
            atomicAdd(&g_deg[d0], 1);
            atomicAdd(&g_deg[d1], 1);
        }
        // --- nodes-per-graph counts (warp 0, batch sorted) ---
        if (tid < 32) {
            int g = batch[tile * 32 + tid];
            unsigned mask = __match_any_sync(0xffffffffu, g);
            if (tid == __ffs(mask) - 1) atomicAdd(&g_cnt[g], __popc(mask));
        }
        // --- load x tile [32 x 128] coalesced ---
#pragma unroll
        for (int i = 0; i < 4; i++) {
            int j = tid + i * 256;       // 0..1023
            int r = j >> 5, cv = j & 31;
            *(float4*)&xs[r * 132 + cv * 4] = x4[(tile * 32 + r) * 32 + cv];
        }
        __syncthreads();
        // --- y = x @ W1f (no bias/relu: folded into gather kernel) ---
        float4 a0 = make_float4(0.f, 0.f, 0.f, 0.f), a1 = a0;
#pragma unroll 8
        for (int k = 0; k < 128; k++) {
            float4 wv = *(const float4*)&W1s[k * 64 + c0];
            float z0 = xs[(m0 + 0) * 132 + k];
            float z1 = xs[(m0 + 1) * 132 + k];
            FMA4(a0, wv, z0);
            FMA4(a1, wv, z1);
        }
        int n0 = tile * 32 + m0;
        *(uint2*)&y0[(n0 + 0) * 64 + c0] = f4_to_h4(a0);
        *(uint2*)&y0[(n0 + 1) * 64 + c0] = f4_to_h4(a1);
    }
}

// ---------------- single-pass decoupled-lookback exclusive scan ----------------
__global__ __launch_bounds__(1024) void k_scanlb() {
    __shared__ int s[1024];
    __shared__ int s_base;
    int t = threadIdx.x, b = blockIdx.x;
    int i = b * 1024 + t;
    int v = (i < NN) ? g_deg[i] : 0;
    s[t] = v;
    __syncthreads();
#pragma unroll
    for (int off = 1; off < 1024; off <<= 1) {
        int u = (t >= off) ? s[t - off] : 0;
        __syncthreads();
        s[t] += u;
        __syncthreads();
    }
    int agg = s[1023];
    if (t == 0) {
        if (b == 0) {
            atomicExch(&g_lb[0], (2ULL << 62) | (unsigned)agg);
            s_base = 0;
        } else {
            atomicExch(&g_lb[b], (1ULL << 62) | (unsigned)agg);
            int running = 0;
            int j = b - 1;
            while (true) {
                unsigned long long xx;
                do { xx = atomicAdd(&g_lb[j], 0ULL); } while ((xx >> 62) == 0);
                running += (int)(unsigned)(xx & 0xffffffffULL);
                if ((xx >> 62) == 2ULL) break;
                j--;
            }
            atomicExch(&g_lb[b], (2ULL << 62) | (unsigned)(running + agg));
            s_base = running;
        }
    }
    __syncthreads();
    if (i < NN) {
        int ex = s[t] - v + s_base;
        g_rowptr[i] = ex;
        g_cursor[i] = ex;
    }
    if (i == 0) g_rowptr[NN] = NE;
}

// fill CSR col (src indices) keyed by dst
__global__ void k_fill(const int* __restrict__ ei) {
    int e = blockIdx.x * blockDim.x + threadIdx.x;
    if (e < NE) {
        int d = ei[NE + e];
        int slot = atomicAdd(&g_cursor[d], 1);
        g_col[slot] = ei[e];
    }
}

// ---------------- gather-only kernel: t = relu(y_self + agg(y) + b1) ----------------
// y in fp16 (128B rows), 8-lane groups x LDG.128, fp32 accumulation.
__global__ __launch_bounds__(256, 6) void k_gather(const __half* __restrict__ yin,
                                                   const float* __restrict__ b1,
                                                   float* __restrict__ tout) {
    int tid = threadIdx.x;
    int l8 = tid & 7;
    int grp = (tid >> 3) & 3;
    const unsigned gm = 0xFFu << (grp * 8);
    int gw = (blockIdx.x * 256 + tid) >> 3;       // global 8-lane group id
    int ngw = (gridDim.x * 256) >> 3;
    const uint4* __restrict__ yin4 = (const uint4*)yin;  // 8 halfs per uint4
    float4* __restrict__ tout4 = (float4*)tout;
    float4 bb0 = *(const float4*)&b1[8 * l8];
    float4 bb1 = *(const float4*)&b1[8 * l8 + 4];

    for (int n = gw; n < NN; n += ngw) {
        float acc[8];
#pragma unroll
        for (int i = 0; i < 8; i++) acc[i] = 0.f;
        add8h(acc, yin4[n * 8 + l8]);  // self term
        int rs = g_rowptr[n];
        int re = g_rowptr[n + 1];
        for (int j0 = rs; j0 < re; j0 += 8) {
            int myc = (j0 + l8 < re) ? g_col[j0 + l8] : 0;
            int cnt = min(8, re - j0);
            int jj = 0;
            for (; jj + 4 <= cnt; jj += 4) {
                int s0 = __shfl_sync(gm, myc, jj, 8);
                int s1 = __shfl_sync(gm, myc, jj + 1, 8);
                int s2 = __shfl_sync(gm, myc, jj + 2, 8);
                int s3 = __shfl_sync(gm, myc, jj + 3, 8);
                uint4 v0 = yin4[s0 * 8 + l8];
                uint4 v1 = yin4[s1 * 8 + l8];
                uint4 v2 = yin4[s2 * 8 + l8];
                uint4 v3 = yin4[s3 * 8 + l8];
                add8h(acc, v0);
                add8h(acc, v1);
                add8h(acc, v2);
                add8h(acc, v3);
            }
            for (; jj < cnt; jj++) {
                int sj = __shfl_sync(gm, myc, jj, 8);
                add8h(acc, yin4[sj * 8 + l8]);
            }
        }
        float4 o0 = make_float4(fmaxf(acc[0] + bb0.x, 0.f), fmaxf(acc[1] + bb0.y, 0.f),
                                fmaxf(acc[2] + bb0.z, 0.f), fmaxf(acc[3] + bb0.w, 0.f));
        float4 o1 = make_float4(fmaxf(acc[4] + bb1.x, 0.f), fmaxf(acc[5] + bb1.y, 0.f),
                                fmaxf(acc[6] + bb1.z, 0.f), fmaxf(acc[7] + bb1.w, 0.f));
        tout4[n * 16 + l8 * 2 + 0] = o0;
        tout4[n * 16 + l8 * 2 + 1] = o1;
    }
}

// ---------------- dense GEMM kernel via packed f32x2 ----------------
// h' = relu(t@W2+b2); pool h'; y_next = h'@W1n (fp16 out).
// FFMA-issue-bound -> k-paired fma.rn.f32x2 halves FFMA instruction count.
// Weights staged pair-major in smem; cols {tx,+16,+32,+48} for conflict-free b64 LDS.
template <bool LAST>
__global__ __launch_bounds__(256) void k_gemm(const float* __restrict__ tin,
                                              const float* __restrict__ W2,
                                              const float* __restrict__ b2,
                                              const float* __restrict__ W1n,
                                              const int* __restrict__ batch,
                                              __half* __restrict__ ynext,
                                              int loff) {
    constexpr int W1N_SZ = LAST ? 0 : 4096;
    extern __shared__ float sm[];
    float* W2s  = sm;                        // pair-major: 4096 words
    float* W1ns = sm + 4096;                 // pair-major (absent when LAST)
    float* b2s  = sm + 4096 + W1N_SZ;        // 64
    float* zsh  = b2s + 64;                  // 64*68 (t tile, then h' in-place)
    __shared__ int sbatch[64];

    int tid = threadIdx.x;
    for (int i = tid; i < 4096; i += 256) {
        int k = i >> 6, c = i & 63;
        W2s[(k >> 1) * 128 + c * 2 + (k & 1)] = W2[i];
    }
    if (!LAST) for (int i = tid; i < 4096; i += 256) {
        int k = i >> 6, c = i & 63;
        W1ns[(k >> 1) * 128 + c * 2 + (k & 1)] = W1n[i];
    }
    if (tid < 64) b2s[tid] = b2[tid];

    const int ty = tid >> 4, tx = tid & 15;
    const int m0 = ty * 4;
    const float4* __restrict__ tin4 = (const float4*)tin;
    const u64* W2p  = (const u64*)W2s;
    const u64* W1np = (const u64*)W1ns;

    for (int tile = blockIdx.x; tile < LTILES; tile += gridDim.x) {
        __syncthreads();  // protect zsh/sbatch from previous iteration's readers
        if (tid < 64) {
            int n = tile * 64 + tid;
            sbatch[tid] = (n < NN) ? batch[n] : 0;
        }
        // ---- stage t tile [64 x 64] into zsh, coalesced ----
#pragma unroll
        for (int i = 0; i < 4; i++) {
            int j = tid + i * 256;          // 0..1023
            int r = j >> 4, cv = j & 15;
            *(float4*)&zsh[r * 68 + cv * 4] = tin4[(tile * 64 + r) * 16 + cv];
        }
        __syncthreads();

        // ---- GEMM1: h' = relu(t @ W2 + b2), f32x2 k-paired ----
        {
            u64 acc[4][4];
#pragma unroll
            for (int r = 0; r < 4; r++)
#pragma unroll
                for (int j = 0; j < 4; j++) acc[r][j] = 0ULL;
#pragma unroll
            for (int kp = 0; kp < 32; kp += 2) {
                ulonglong2 zp0 = *(const ulonglong2*)&zsh[(m0 + 0) * 68 + 2 * kp];
                ulonglong2 zp1 = *(const ulonglong2*)&zsh[(m0 + 1) * 68 + 2 * kp];
                ulonglong2 zp2 = *(const ulonglong2*)&zsh[(m0 + 2) * 68 + 2 * kp];
                ulonglong2 zp3 = *(const ulonglong2*)&zsh[(m0 + 3) * 68 + 2 * kp];
                u64 wa0 = W2p[kp * 64 + tx +  0];
                u64 wa1 = W2p[kp * 64 + tx + 16];
                u64 wa2 = W2p[kp * 64 + tx + 32];
                u64 wa3 = W2p[kp * 64 + tx + 48];
                u64 wb0 = W2p[(kp + 1) * 64 + tx +  0];
                u64 wb1 = W2p[(kp + 1) * 64 + tx + 16];
                u64 wb2 = W2p[(kp + 1) * 64 + tx + 32];
                u64 wb3 = W2p[(kp + 1) * 64 + tx + 48];
                fma2(acc[0][0], zp0.x, wa0); fma2(acc[0][1], zp0.x, wa1);
                fma2(acc[0][2], zp0.x, wa2); fma2(acc[0][3], zp0.x, wa3);
                fma2(acc[0][0], zp0.y, wb0); fma2(acc[0][1], zp0.y, wb1);
                fma2(acc[0][2], zp0.y, wb2); fma2(acc[0][3], zp0.y, wb3);
                fma2(acc[1][0], zp1.x, wa0); fma2(acc[1][1], zp1.x, wa1);
                fma2(acc[1][2], zp1.x, wa2); fma2(acc[1][3], zp1.x, wa3);
                fma2(acc[1][0], zp1.y, wb0); fma2(acc[1][1], zp1.y, wb1);
                fma2(acc[1][2], zp1.y, wb2); fma2(acc[1][3], zp1.y, wb3);
                fma2(acc[2][0], zp2.x, wa0); fma2(acc[2][1], zp2.x, wa1);
                fma2(acc[2][2], zp2.x, wa2); fma2(acc[2][3], zp2.x, wa3);
                fma2(acc[2][0], zp2.y, wb0); fma2(acc[2][1], zp2.y, wb1);
                fma2(acc[2][2], zp2.y, wb2); fma2(acc[2][3], zp2.y, wb3);
                fma2(acc[3][0], zp3.x, wa0); fma2(acc[3][1], zp3.x, wa1);
                fma2(acc[3][2], zp3.x, wa2); fma2(acc[3][3], zp3.x, wa3);
                fma2(acc[3][0], zp3.y, wb0); fma2(acc[3][1], zp3.y, wb1);
                fma2(acc[3][2], zp3.y, wb2); fma2(acc[3][3], zp3.y, wb3);
            }
            __syncthreads();  // all GEMM1 reads of zsh complete before overwrite
#pragma unroll
            for (int r = 0; r < 4; r++)
#pragma unroll
                for (int j = 0; j < 4; j++) {
                    int c = tx + 16 * j;
                    zsh[(m0 + r) * 68 + c] = fmaxf(unpk_add(acc[r][j]) + b2s[c], 0.f);
                }
        }
        __syncthreads();  // h' visible to all

        // ---- GEMM2: y_next = h' @ W1next -> global fp16 (skipped on last layer) ----
        if (!LAST) {
            u64 acc[4][4];
#pragma unroll
            for (int r = 0; r < 4; r++)
#pragma unroll
                for (int j = 0; j < 4; j++) acc[r][j] = 0ULL;
#pragma unroll
            for (int kp = 0; kp < 32; kp += 2) {
                ulonglong2 zp0 = *(const ulonglong2*)&zsh[(m0 + 0) * 68 + 2 * kp];
                ulonglong2 zp1 = *(const ulonglong2*)&zsh[(m0 + 1) * 68 + 2 * kp];
                ulonglong2 zp2 = *(const ulonglong2*)&zsh[(m0 + 2) * 68 + 2 * kp];
                ulonglong2 zp3 = *(const ulonglong2*)&zsh[(m0 + 3) * 68 + 2 * kp];
                u64 wa0 = W1np[kp * 64 + tx +  0];
                u64 wa1 = W1np[kp * 64 + tx + 16];
                u64 wa2 = W1np[kp * 64 + tx + 32];
                u64 wa3 = W1np[kp * 64 + tx + 48];
                u64 wb0 = W1np[(kp + 1) * 64 + tx +  0];
                u64 wb1 = W1np[(kp + 1) * 64 + tx + 16];
                u64 wb2 = W1np[(kp + 1) * 64 + tx + 32];
                u64 wb3 = W1np[(kp + 1) * 64 + tx + 48];
                fma2(acc[0][0], zp0.x, wa0); fma2(acc[0][1], zp0.x, wa1);
                fma2(acc[0][2], zp0.x, wa2); fma2(acc[0][3], zp0.x, wa3);
                fma2(acc[0][0], zp0.y, wb0); fma2(acc[0][1], zp0.y, wb1);
                fma2(acc[0][2], zp0.y, wb2); fma2(acc[0][3], zp0.y, wb3);
                fma2(acc[1][0], zp1.x, wa0); fma2(acc[1][1], zp1.x, wa1);
                fma2(acc[1][2], zp1.x, wa2); fma2(acc[1][3], zp1.x, wa3);
                fma2(acc[1][0], zp1.y, wb0); fma2(acc[1][1], zp1.y, wb1);
                fma2(acc[1][2], zp1.y, wb2); fma2(acc[1][3], zp1.y, wb3);
                fma2(acc[2][0], zp2.x, wa0); fma2(acc[2][1], zp2.x, wa1);
                fma2(acc[2][2], zp2.x, wa2); fma2(acc[2][3], zp2.x, wa3);
                fma2(acc[2][0], zp2.y, wb0); fma2(acc[2][1], zp2.y, wb1);
                fma2(acc[2][2], zp2.y, wb2); fma2(acc[2][3], zp2.y, wb3);
                fma2(acc[3][0], zp3.x, wa0); fma2(acc[3][1], zp3.x, wa1);
                fma2(acc[3][2], zp3.x, wa2); fma2(acc[3][3], zp3.x, wa3);
                fma2(acc[3][0], zp3.y, wb0); fma2(acc[3][1], zp3.y, wb1);
                fma2(acc[3][2], zp3.y, wb2); fma2(acc[3][3], zp3.y, wb3);
            }
            int n0 = tile * 64 + m0;
#pragma unroll
            for (int r = 0; r < 4; r++)
#pragma unroll
                for (int j = 0; j < 4; j++) {
                    int c = tx + 16 * j;
                    ynext[(n0 + r) * 64 + c] = __float2half(unpk_add(acc[r][j]));
                }
        }

        // ---- pooling of h' (batch sorted: run-accumulate + flush) ----
        {
            int c = tid & 63, sg = tid >> 6;  // 4 groups x 16 rows
            float acc = 0.f;
            int curg = -1;
            for (int r = sg * 16; r < sg * 16 + 16; r++) {
                int n = tile * 64 + r;
                if (n >= NN) break;
                int g = sbatch[r];
                if (g != curg) {
                    if (curg >= 0) atomicAdd(&g_pool[curg * 256 + loff + c], acc);
                    acc = 0.f;
                    curg = g;
                }
                acc += zsh[r * 68 + c];
            }
            if (curg >= 0) atomicAdd(&g_pool[curg * 256 + loff + c], acc);
        }
    }
}

// ---------------- JK projection at graph granularity ----------------
__global__ void k_jk(const float* __restrict__ Wjk, const float* __restrict__ bjk) {
    int g = blockIdx.x;
    int c = threadIdx.x;  // 64
    float acc = (float)g_cnt[g] * bjk[c];
#pragma unroll 4
    for (int k = 0; k < 256; k++) acc += g_pool[g * 256 + k] * Wjk[k * 64 + c];
    g_pooledT[c * NG + g] = acc;
}

// ---------------- classifier: Linear -> BN(batch stats) -> ReLU -> Linear ----------------
__global__ __launch_bounds__(128) void k_final(const float* __restrict__ Wc1,
                                               const float* __restrict__ bc1,
                                               const float* __restrict__ gamma,
                                               const float* __restrict__ beta,
                                               const float* __restrict__ Wc2,
                                               const float* __restrict__ bc2,
                                               float* __restrict__ out) {
    extern __shared__ float sm[];
    float* Wc1s = sm;                  // 4096
    float* zsh = Wc1s + 4096;          // 128*66
    float* scv = zsh + 128 * 66;       // 64
    float* shv = scv + 64;             // 64
    int tid = threadIdx.x;  // = graph index g
    for (int i = tid; i < 4096; i += 128) Wc1s[i] = Wc1[i];
    __syncthreads();

    float4 acc4[16];
#pragma unroll
    for (int c = 0; c < 16; c++) acc4[c] = *(const float4*)&bc1[c * 4];
    for (int k = 0; k < 64; k++) {
        float pk = g_pooledT[k * NG + tid];
#pragma unroll
        for (int c = 0; c < 16; c++) {
            float4 wv = *(const float4*)&Wc1s[k * 64 + c * 4];
            acc4[c].x += pk * wv.x; acc4[c].y += pk * wv.y;
            acc4[c].z += pk * wv.z; acc4[c].w += pk * wv.w;
        }
    }
#pragma unroll
    for (int c = 0; c < 16; c++) {
        zsh[tid * 66 + c * 4 + 0] = acc4[c].x;
        zsh[tid * 66 + c * 4 + 1] = acc4[c].y;
        zsh[tid * 66 + c * 4 + 2] = acc4[c].z;
        zsh[tid * 66 + c * 4 + 3] = acc4[c].w;
    }
    __syncthreads();

    if (tid < 64) {
        float s = 0.f, s2 = 0.f;
        for (int g = 0; g < 128; g++) {
            float v = zsh[g * 66 + tid];
            s += v;
            s2 += v * v;
        }
        float mu = s * (1.0f / 128.0f);
        float var = s2 * (1.0f / 128.0f) - mu * mu;
        float sc = gamma[tid] * rsqrtf(var + 1e-5f);
        scv[tid] = sc;
        shv[tid] = beta[tid] - mu * sc;
    }
    __syncthreads();

    float ao[10];
#pragma unroll
    for (int o = 0; o < 10; o++) ao[o] = bc2[o];
    for (int c = 0; c < 64; c++) {
        float v = fmaxf(zsh[tid * 66 + c] * scv[c] + shv[c], 0.0f);
#pragma unroll
        for (int o = 0; o < 10; o++) ao[o] += v * Wc2[c * 10 + o];
    }
#pragma unroll
    for (int o = 0; o < 10; o++) out[tid * 10 + o] = ao[o];
}

// ---------------- end-of-call zeroing (prepares NEXT call) ----------------
__global__ void k_zero_post() {
    int i = blockIdx.x * blockDim.x + threadIdx.x;
    int stride = gridDim.x * blockDim.x;
    for (int j = i; j < NN; j += stride) g_deg[j] = 0;
    for (int j = i; j < NG * 4 * HID; j += stride) g_pool[j] = 0.0f;
    for (int j = i; j < NG; j += stride) g_cnt[j] = 0;
    for (int j = i; j < NB; j += stride) g_lb[j] = 0ULL;
}

// ---------------- launch ----------------
extern "C" void kernel_launch(void* const* d_in, const int* in_sizes, int n_in,
                              void* d_out, int out_size) {
    const float* x    = (const float*)d_in[0];
    const int*   ei   = (const int*)d_in[1];
    const int*   batch= (const int*)d_in[2];
    const float* W1f  = (const float*)d_in[3];
    const float* b1f  = (const float*)d_in[4];
    const float* W2f  = (const float*)d_in[5];
    const float* b2f  = (const float*)d_in[6];
    const float* W1r  = (const float*)d_in[7];
    const float* b1r  = (const float*)d_in[8];
    const float* W2r  = (const float*)d_in[9];
    const float* b2r  = (const float*)d_in[10];
    const float* Wjk  = (const float*)d_in[11];
    const float* bjk  = (const float*)d_in[12];
    const float* Wc1  = (const float*)d_in[13];
    const float* bc1  = (const float*)d_in[14];
    const float* gamma= (const float*)d_in[15];
    const float* beta = (const float*)d_in[16];
    const float* Wc2  = (const float*)d_in[17];
    const float* bc2  = (const float*)d_in[18];
    float* out = (float*)d_out;

    __half* yp = 0;
    float*  tp = 0;
    cudaGetSymbolAddress((void**)&yp, g_y);
    cudaGetSymbolAddress((void**)&tp, g_t);

    const size_t smp  = (size_t)(8192 + 32 * 132) * sizeof(float);
    const size_t smg  = (size_t)(4096 + 4096 + 64 + 64 * 68) * sizeof(float);
    const size_t smgl = (size_t)(4096 + 64 + 64 * 68) * sizeof(float);
    const size_t smf  = (size_t)(4096 + 128 * 66 + 128) * sizeof(float);
    cudaFuncSetAttribute(k_pre_hist,    cudaFuncAttributeMaxDynamicSharedMemorySize, (int)smp);
    cudaFuncSetAttribute(k_gemm<false>, cudaFuncAttributeMaxDynamicSharedMemorySize, (int)smg);
    cudaFuncSetAttribute(k_gemm<true>,  cudaFuncAttributeMaxDynamicSharedMemorySize, (int)smgl);
    cudaFuncSetAttribute(k_final,       cudaFuncAttributeMaxDynamicSharedMemorySize, (int)smf);

    // launch 0: dense pre-GEMM (fp16 y out) + histograms (+ pad zeroing)
    k_pre_hist<<<592, 256, smp>>>(x, W1f, ei, batch, yp, tp);
    // launch 1-2: CSR
    k_scanlb<<<NB, 1024>>>();
    k_fill<<<(NE + 255) / 256, 256>>>(ei);

    // per layer: gather (y->t, fp16 gather), then dense gemm (t -> pool + y_next fp16)
    // launch 3 (profiled slot): gather layer 0
    k_gather<<<888, 256>>>(yp, b1f, tp);
    k_gemm<false><<<592, 256, smg>>>(tp, W2f, b2f, W1r, batch, yp, 0);
    k_gather<<<888, 256>>>(yp, b1r, tp);
    k_gemm<false><<<592, 256, smg>>>(tp, W2r, b2r, W1r + 4096, batch, yp, 64);
    k_gather<<<888, 256>>>(yp, b1r + 64, tp);
    k_gemm<false><<<592, 256, smg>>>(tp, W2r + 4096, b2r + 64, W1r + 2 * 4096, batch, yp, 128);
    k_gather<<<888, 256>>>(yp, b1r + 128, tp);
    k_gemm<true><<<592, 256, smgl>>>(tp, W2r + 2 * 4096, b2r + 128, nullptr, batch, nullptr, 192);

    // graph-granularity tail
    k_jk<<<NG, 64>>>(Wjk, bjk);
    k_final<<<1, 128, smf>>>(Wc1, bc1, gamma, beta, Wc2, bc2, out);

    // zero accumulators for the NEXT call (after all readers above)
    k_zero_post<<<256, 256>>>();
}

// round 12
// speedup vs baseline: 1.2621x; 1.2621x over previous
#include <cuda_runtime.h>
#include <cuda_fp16.h>
#include <mma.h>

using namespace nvcuda;

#define NN 100000
#define NNP 100032   // padded to 64-row tiles
#define NE 1600000
#define NG 128
#define HID 64
#define NB 98        // ceil(NN / 1024)
#define NTILES 3125  // NN / 32  (pre_hist tiles)
#define LTILES 1563  // ceil(NN / 64) (gemm tiles)

#define FMA4(acc, wv, sv) { (acc).x += (sv) * (wv).x; (acc).y += (sv) * (wv).y; \
                            (acc).z += (sv) * (wv).z; (acc).w += (sv) * (wv).w; }

// ---------------- scratch (device globals: allocation-free) ----------------
// accumulated-into buffers (g_deg, g_pool, g_cnt, g_lb) are zeroed at the END
// of each kernel_launch (k_zero_post). Module-load zero-init covers call 1.
__device__ int    g_deg[NN];
__device__ int    g_rowptr[NN + 1];
__device__ int    g_cursor[NN];
__device__ int    g_col[NE];
__device__ unsigned long long g_lb[NB];  // lookback scan state (flag<<62 | value)
__device__ __half g_y[NNP * HID];        // y = h@W1, fp16 (gathered operand)
__device__ __half g_t[NNP * HID];        // t = relu(y_self+agg+b1), fp16 (GEMM A operand)
__device__ float  g_pool[NG * 4 * HID];  // pooled per-layer h', [G][256]
__device__ int    g_cnt[NG];
__device__ float  g_pooledT[HID * NG];   // JK output, transposed [c][g]

// convert float4 -> 4 packed halfs (uint2)
__device__ __forceinline__ uint2 f4_to_h4(float4 a) {
    __half2 lo = __floats2half2_rn(a.x, a.y);
    __half2 hi = __floats2half2_rn(a.z, a.w);
    uint2 r;
    r.x = *(unsigned*)&lo;
    r.y = *(unsigned*)&hi;
    return r;
}
// accumulate 8 packed halfs (uint4) into float acc[8]
__device__ __forceinline__ void add8h(float* a, uint4 v) {
    float2 f;
    f = __half22float2(*(__half2*)&v.x); a[0] += f.x; a[1] += f.y;
    f = __half22float2(*(__half2*)&v.y); a[2] += f.x; a[3] += f.y;
    f = __half22float2(*(__half2*)&v.z); a[4] += f.x; a[5] += f.y;
    f = __half22float2(*(__half2*)&v.w); a[6] += f.x; a[7] += f.y;
}

// ---------------- launch 0: fused y0 = x @ W1f (fp16 out) + histograms ----------------
__global__ __launch_bounds__(256) void k_pre_hist(const float* __restrict__ x,
                                                  const float* __restrict__ W1f,
                                                  const int* __restrict__ ei,
                                                  const int* __restrict__ batch,
                                                  __half* __restrict__ y0,
                                                  __half* __restrict__ t0) {
    extern __shared__ float sm[];
    float* W1s = sm;          // 128*64 = 8192
    float* xs  = sm + 8192;   // 32*132
    int tid = threadIdx.x;
    for (int i = tid; i < 8192; i += 256) W1s[i] = W1f[i];
    // zero the pad rows (NN..NNP-1) of y and t (both half), once per call
    if (blockIdx.x == 0) {
        unsigned* yz = (unsigned*)(y0 + NN * 64);     // 2048 halfs = 1024 u32
        unsigned* tz = (unsigned*)(t0 + NN * 64);
        for (int i = tid; i < (NNP - NN) * 32; i += 256) { yz[i] = 0u; tz[i] = 0u; }
    }
    const int ty = tid >> 4, tx = tid & 15;
    const int m0 = ty * 2, c0 = tx * 4;
    const float4* __restrict__ x4 = (const float4*)x;

    for (int tile = blockIdx.x; tile < NTILES; tile += gridDim.x) {
        __syncthreads();
        // --- degree histogram: 512 edges per tile (3125*512 = NE exactly) ---
        {
            int e0 = tile * 512;
            int d0 = ei[NE + e0 + tid];
            int d1 = ei[NE + e0 + 256 + tid];
            atomicAdd(&g_deg[d0], 1);
            atomicAdd(&g_deg[d1], 1);
        }
        // --- nodes-per-graph counts (warp 0, batch sorted) ---
        if (tid < 32) {
            int g = batch[tile * 32 + tid];
            unsigned mask = __match_any_sync(0xffffffffu, g);
            if (tid == __ffs(mask) - 1) atomicAdd(&g_cnt[g], __popc(mask));
        }
        // --- load x tile [32 x 128] coalesced ---
#pragma unroll
        for (int i = 0; i < 4; i++) {
            int j = tid + i * 256;       // 0..1023
            int r = j >> 5, cv = j & 31;
            *(float4*)&xs[r * 132 + cv * 4] = x4[(tile * 32 + r) * 32 + cv];
        }
        __syncthreads();
        // --- y = x @ W1f (no bias/relu: folded into gather kernel) ---
        float4 a0 = make_float4(0.f, 0.f, 0.f, 0.f), a1 = a0;
#pragma unroll 8
        for (int k = 0; k < 128; k++) {
            float4 wv = *(const float4*)&W1s[k * 64 + c0];
            float z0 = xs[(m0 + 0) * 132 + k];
            float z1 = xs[(m0 + 1) * 132 + k];
            FMA4(a0, wv, z0);
            FMA4(a1, wv, z1);
        }
        int n0 = tile * 32 + m0;
        *(uint2*)&y0[(n0 + 0) * 64 + c0] = f4_to_h4(a0);
        *(uint2*)&y0[(n0 + 1) * 64 + c0] = f4_to_h4(a1);
    }
}

// ---------------- single-pass decoupled-lookback exclusive scan ----------------
__global__ __launch_bounds__(1024) void k_scanlb() {
    __shared__ int s[1024];
    __shared__ int s_base;
    int t = threadIdx.x, b = blockIdx.x;
    int i = b * 1024 + t;
    int v = (i < NN) ? g_deg[i] : 0;
    s[t] = v;
    __syncthreads();
#pragma unroll
    for (int off = 1; off < 1024; off <<= 1) {
        int u = (t >= off) ? s[t - off] : 0;
        __syncthreads();
        s[t] += u;
        __syncthreads();
    }
    int agg = s[1023];
    if (t == 0) {
        if (b == 0) {
            atomicExch(&g_lb[0], (2ULL << 62) | (unsigned)agg);
            s_base = 0;
        } else {
            atomicExch(&g_lb[b], (1ULL << 62) | (unsigned)agg);
            int running = 0;
            int j = b - 1;
            while (true) {
                unsigned long long xx;
                do { xx = atomicAdd(&g_lb[j], 0ULL); } while ((xx >> 62) == 0);
                running += (int)(unsigned)(xx & 0xffffffffULL);
                if ((xx >> 62) == 2ULL) break;
                j--;
            }
            atomicExch(&g_lb[b], (2ULL << 62) | (unsigned)(running + agg));
            s_base = running;
        }
    }
    __syncthreads();
    if (i < NN) {
        int ex = s[t] - v + s_base;
        g_rowptr[i] = ex;
        g_cursor[i] = ex;
    }
    if (i == 0) g_rowptr[NN] = NE;
}

// fill CSR col (src indices) keyed by dst
__global__ void k_fill(const int* __restrict__ ei) {
    int e = blockIdx.x * blockDim.x + threadIdx.x;
    if (e < NE) {
        int d = ei[NE + e];
        int slot = atomicAdd(&g_cursor[d], 1);
        g_col[slot] = ei[e];
    }
}

// ---------------- gather-only kernel: t = relu(y_self + agg(y) + b1), fp16 out ----
// y in fp16 (128B rows), 8-lane groups x LDG.128, fp32 accumulation.
__global__ __launch_bounds__(256, 6) void k_gather(const __half* __restrict__ yin,
                                                   const float* __restrict__ b1,
                                                   __half* __restrict__ tout) {
    int tid = threadIdx.x;
    int l8 = tid & 7;
    int grp = (tid >> 3) & 3;
    const unsigned gm = 0xFFu << (grp * 8);
    int gw = (blockIdx.x * 256 + tid) >> 3;       // global 8-lane group id
    int ngw = (gridDim.x * 256) >> 3;
    const uint4* __restrict__ yin4 = (const uint4*)yin;  // 8 halfs per uint4
    uint4* __restrict__ tout4 = (uint4*)tout;
    float4 bb0 = *(const float4*)&b1[8 * l8];
    float4 bb1 = *(const float4*)&b1[8 * l8 + 4];

    for (int n = gw; n < NN; n += ngw) {
        float acc[8];
#pragma unroll
        for (int i = 0; i < 8; i++) acc[i] = 0.f;
        add8h(acc, yin4[n * 8 + l8]);  // self term
        int rs = g_rowptr[n];
        int re = g_rowptr[n + 1];
        for (int j0 = rs; j0 < re; j0 += 8) {
            int myc = (j0 + l8 < re) ? g_col[j0 + l8] : 0;
            int cnt = min(8, re - j0);
            int jj = 0;
            for (; jj + 4 <= cnt; jj += 4) {
                int s0 = __shfl_sync(gm, myc, jj, 8);
                int s1 = __shfl_sync(gm, myc, jj + 1, 8);
                int s2 = __shfl_sync(gm, myc, jj + 2, 8);
                int s3 = __shfl_sync(gm, myc, jj + 3, 8);
                uint4 v0 = yin4[s0 * 8 + l8];
                uint4 v1 = yin4[s1 * 8 + l8];
                uint4 v2 = yin4[s2 * 8 + l8];
                uint4 v3 = yin4[s3 * 8 + l8];
                add8h(acc, v0);
                add8h(acc, v1);
                add8h(acc, v2);
                add8h(acc, v3);
            }
            for (; jj < cnt; jj++) {
                int sj = __shfl_sync(gm, myc, jj, 8);
                add8h(acc, yin4[sj * 8 + l8]);
            }
        }
        float4 o0 = make_float4(fmaxf(acc[0] + bb0.x, 0.f), fmaxf(acc[1] + bb0.y, 0.f),
                                fmaxf(acc[2] + bb0.z, 0.f), fmaxf(acc[3] + bb0.w, 0.f));
        float4 o1 = make_float4(fmaxf(acc[4] + bb1.x, 0.f), fmaxf(acc[5] + bb1.y, 0.f),
                                fmaxf(acc[6] + bb1.z, 0.f), fmaxf(acc[7] + bb1.w, 0.f));
        uint2 p0 = f4_to_h4(o0);
        uint2 p1 = f4_to_h4(o1);
        uint4 pk;
        pk.x = p0.x; pk.y = p0.y; pk.z = p1.x; pk.w = p1.y;
        tout4[n * 8 + l8] = pk;
    }
}

// ---------------- tensor-core GEMM kernel (wmma m16n16k16, fp16 in / fp32 acc) ----
// h' = relu(t@W2+b2); pool h'; y_next = h'@W1n (fp16 out).
// 64-row tiles, 256 threads (8 warps); warp w -> row-block w&3, col-blocks 2*(w>>2)+{0,1}.
template <bool LAST>
__global__ __launch_bounds__(256) void k_gemm(const __half* __restrict__ tin,
                                              const float* __restrict__ W2,
                                              const float* __restrict__ b2,
                                              const float* __restrict__ W1n,
                                              const int* __restrict__ batch,
                                              __half* __restrict__ ynext,
                                              int loff) {
    extern __shared__ char smc[];
    // layout (all 16B-aligned): W2h[64][72]h, (W1nh[64][72]h), ts[64][72]h, hs[64][72]h, f32s[64][68]f
    __half* W2h  = (__half*)smc;                                  // 9216 B
    __half* W1nh = (__half*)(smc + 9216);                         // 9216 B (absent when LAST)
    __half* ts   = (__half*)(smc + 9216 + (LAST ? 0 : 9216));     // 9216 B
    __half* hs   = ts + 64 * 72;                                  // 9216 B
    float*  f32s = (float*)(hs + 64 * 72);                        // 17408 B
    __shared__ int   sbatch[64];
    __shared__ float b2s[64];

    int tid = threadIdx.x;
    const int warp = tid >> 5;
    const int rb = warp & 3;             // row block (16 rows)
    const int cb0 = (warp >> 2) * 2;     // first of 2 col blocks

    // stage weights as fp16 (once per block)
    for (int i = tid; i < 4096; i += 256) {
        int k = i >> 6, c = i & 63;
        W2h[k * 72 + c] = __float2half(W2[i]);
    }
    if (!LAST) {
        for (int i = tid; i < 4096; i += 256) {
            int k = i >> 6, c = i & 63;
            W1nh[k * 72 + c] = __float2half(W1n[i]);
        }
    }
    if (tid < 64) b2s[tid] = b2[tid];

    const uint4* __restrict__ tin4 = (const uint4*)tin;  // 8 halfs per uint4

    for (int tile = blockIdx.x; tile < LTILES; tile += gridDim.x) {
        __syncthreads();  // protect ts/hs/f32s/sbatch from previous iteration
        if (tid < 64) {
            int n = tile * 64 + tid;
            sbatch[tid] = (n < NN) ? batch[n] : 0;
        }
        // ---- stage t tile [64 x 64] fp16 into ts (512 uint4, 2 per thread) ----
#pragma unroll
        for (int i = 0; i < 2; i++) {
            int j = tid + i * 256;          // 0..511
            int r = j >> 3, cv = j & 7;     // 8 uint4 per row
            *(uint4*)&ts[r * 72 + cv * 8] = tin4[(tile * 64 + r) * 8 + cv];
        }
        __syncthreads();

        // ---- GEMM1: D1 = t @ W2 (HMMA), store fp32 to f32s ----
        {
            wmma::fragment<wmma::accumulator, 16, 16, 16, float> acc0, acc1;
            wmma::fill_fragment(acc0, 0.0f);
            wmma::fill_fragment(acc1, 0.0f);
#pragma unroll
            for (int kb = 0; kb < 4; kb++) {
                wmma::fragment<wmma::matrix_a, 16, 16, 16, __half, wmma::row_major> af;
                wmma::load_matrix_sync(af, ts + (rb * 16) * 72 + kb * 16, 72);
                wmma::fragment<wmma::matrix_b, 16, 16, 16, __half, wmma::row_major> bf;
                wmma::load_matrix_sync(bf, W2h + (kb * 16) * 72 + cb0 * 16, 72);
                wmma::mma_sync(acc0, af, bf, acc0);
                wmma::load_matrix_sync(bf, W2h + (kb * 16) * 72 + (cb0 + 1) * 16, 72);
                wmma::mma_sync(acc1, af, bf, acc1);
            }
            wmma::store_matrix_sync(f32s + (rb * 16) * 68 + cb0 * 16, acc0, 68, wmma::mem_row_major);
            wmma::store_matrix_sync(f32s + (rb * 16) * 68 + (cb0 + 1) * 16, acc1, 68, wmma::mem_row_major);
        }
        __syncthreads();

        // ---- bias + relu (fp32), keep in f32s for pooling; write hs fp16 for GEMM2 ----
        for (int i = tid; i < 4096; i += 256) {
            int r = i >> 6, c = i & 63;
            float v = fmaxf(f32s[r * 68 + c] + b2s[c], 0.0f);
            f32s[r * 68 + c] = v;
            hs[r * 72 + c] = __float2half(v);
        }
        __syncthreads();

        // ---- pooling of h' (batch sorted: run-accumulate + flush) ----
        {
            int c = tid & 63, sg = tid >> 6;  // 4 groups x 16 rows
            float acc = 0.f;
            int curg = -1;
            for (int r = sg * 16; r < sg * 16 + 16; r++) {
                int n = tile * 64 + r;
                if (n >= NN) break;
                int g = sbatch[r];
                if (g != curg) {
                    if (curg >= 0) atomicAdd(&g_pool[curg * 256 + loff + c], acc);
                    acc = 0.f;
                    curg = g;
                }
                acc += f32s[r * 68 + c];
            }
            if (curg >= 0) atomicAdd(&g_pool[curg * 256 + loff + c], acc);
        }

        // ---- GEMM2: y_next = h' @ W1n (HMMA) -> fp16 global (skipped on last layer) ----
        if (!LAST) {
            wmma::fragment<wmma::accumulator, 16, 16, 16, float> acc0, acc1;
            wmma::fill_fragment(acc0, 0.0f);
            wmma::fill_fragment(acc1, 0.0f);
#pragma unroll
            for (int kb = 0; kb < 4; kb++) {
                wmma::fragment<wmma::matrix_a, 16, 16, 16, __half, wmma::row_major> af;
                wmma::load_matrix_sync(af, hs + (rb * 16) * 72 + kb * 16, 72);
                wmma::fragment<wmma::matrix_b, 16, 16, 16, __half, wmma::row_major> bf;
                wmma::load_matrix_sync(bf, W1nh + (kb * 16) * 72 + cb0 * 16, 72);
                wmma::mma_sync(acc0, af, bf, acc0);
                wmma::load_matrix_sync(bf, W1nh + (kb * 16) * 72 + (cb0 + 1) * 16, 72);
                wmma::mma_sync(acc1, af, bf, acc1);
            }
            __syncthreads();  // pooling reads of f32s complete before overwrite
            wmma::store_matrix_sync(f32s + (rb * 16) * 68 + cb0 * 16, acc0, 68, wmma::mem_row_major);
            wmma::store_matrix_sync(f32s + (rb * 16) * 68 + (cb0 + 1) * 16, acc1, 68, wmma::mem_row_major);
            __syncthreads();
            // convert + write y (coalesced)
            for (int i = tid; i < 4096; i += 256) {
                int r = i >> 6, c = i & 63;
                ynext[(tile * 64 + r) * 64 + c] = __float2half(f32s[r * 68 + c]);
            }
        }
    }
}

// ---------------- JK projection at graph granularity ----------------
__global__ void k_jk(const float* __restrict__ Wjk, const float* __restrict__ bjk) {
    int g = blockIdx.x;
    int c = threadIdx.x;  // 64
    float acc = (float)g_cnt[g] * bjk[c];
#pragma unroll 4
    for (int k = 0; k < 256; k++) acc += g_pool[g * 256 + k] * Wjk[k * 64 + c];
    g_pooledT[c * NG + g] = acc;
}

// ---------------- classifier: Linear -> BN(batch stats) -> ReLU -> Linear ----------------
__global__ __launch_bounds__(128) void k_final(const float* __restrict__ Wc1,
                                               const float* __restrict__ bc1,
                                               const float* __restrict__ gamma,
                                               const float* __restrict__ beta,
                                               const float* __restrict__ Wc2,
                                               const float* __restrict__ bc2,
                                               float* __restrict__ out) {
    extern __shared__ float sm[];
    float* Wc1s = sm;                  // 4096
    float* zsh = Wc1s + 4096;          // 128*66
    float* scv = zsh + 128 * 66;       // 64
    float* shv = scv + 64;             // 64
    int tid = threadIdx.x;  // = graph index g
    for (int i = tid; i < 4096; i += 128) Wc1s[i] = Wc1[i];
    __syncthreads();

    float4 acc4[16];
#pragma unroll
    for (int c = 0; c < 16; c++) acc4[c] = *(const float4*)&bc1[c * 4];
    for (int k = 0; k < 64; k++) {
        float pk = g_pooledT[k * NG + tid];
#pragma unroll
        for (int c = 0; c < 16; c++) {
            float4 wv = *(const float4*)&Wc1s[k * 64 + c * 4];
            acc4[c].x += pk * wv.x; acc4[c].y += pk * wv.y;
            acc4[c].z += pk * wv.z; acc4[c].w += pk * wv.w;
        }
    }
#pragma unroll
    for (int c = 0; c < 16; c++) {
        zsh[tid * 66 + c * 4 + 0] = acc4[c].x;
        zsh[tid * 66 + c * 4 + 1] = acc4[c].y;
        zsh[tid * 66 + c * 4 + 2] = acc4[c].z;
        zsh[tid * 66 + c * 4 + 3] = acc4[c].w;
    }
    __syncthreads();

    if (tid < 64) {
        float s = 0.f, s2 = 0.f;
        for (int g = 0; g < 128; g++) {
            float v = zsh[g * 66 + tid];
            s += v;
            s2 += v * v;
        }
        float mu = s * (1.0f / 128.0f);
        float var = s2 * (1.0f / 128.0f) - mu * mu;
        float sc = gamma[tid] * rsqrtf(var + 1e-5f);
        scv[tid] = sc;
        shv[tid] = beta[tid] - mu * sc;
    }
    __syncthreads();

    float ao[10];
#pragma unroll
    for (int o = 0; o < 10; o++) ao[o] = bc2[o];
    for (int c = 0; c < 64; c++) {
        float v = fmaxf(zsh[tid * 66 + c] * scv[c] + shv[c], 0.0f);
#pragma unroll
        for (int o = 0; o < 10; o++) ao[o] += v * Wc2[c * 10 + o];
    }
#pragma unroll
    for (int o = 0; o < 10; o++) out[tid * 10 + o] = ao[o];
}

// ---------------- end-of-call zeroing (prepares NEXT call) ----------------
__global__ void k_zero_post() {
    int i = blockIdx.x * blockDim.x + threadIdx.x;
    int stride = gridDim.x * blockDim.x;
    for (int j = i; j < NN; j += stride) g_deg[j] = 0;
    for (int j = i; j < NG * 4 * HID; j += stride) g_pool[j] = 0.0f;
    for (int j = i; j < NG; j += stride) g_cnt[j] = 0;
    for (int j = i; j < NB; j += stride) g_lb[j] = 0ULL;
}

// ---------------- launch ----------------
extern "C" void kernel_launch(void* const* d_in, const int* in_sizes, int n_in,
                              void* d_out, int out_size) {
    const float* x    = (const float*)d_in[0];
    const int*   ei   = (const int*)d_in[1];
    const int*   batch= (const int*)d_in[2];
    const float* W1f  = (const float*)d_in[3];
    const float* b1f  = (const float*)d_in[4];
    const float* W2f  = (const float*)d_in[5];
    const float* b2f  = (const float*)d_in[6];
    const float* W1r  = (const float*)d_in[7];
    const float* b1r  = (const float*)d_in[8];
    const float* W2r  = (const float*)d_in[9];
    const float* b2r  = (const float*)d_in[10];
    const float* Wjk  = (const float*)d_in[11];
    const float* bjk  = (const float*)d_in[12];
    const float* Wc1  = (const float*)d_in[13];
    const float* bc1  = (const float*)d_in[14];
    const float* gamma= (const float*)d_in[15];
    const float* beta = (const float*)d_in[16];
    const float* Wc2  = (const float*)d_in[17];
    const float* bc2  = (const float*)d_in[18];
    float* out = (float*)d_out;

    __half* yp = 0;
    __half* tp = 0;
    cudaGetSymbolAddress((void**)&yp, g_y);
    cudaGetSymbolAddress((void**)&tp, g_t);

    const size_t smp  = (size_t)(8192 + 32 * 132) * sizeof(float);
    const size_t smg  = 9216 * 4 + 17408;   // W2h + W1nh + ts + hs + f32s
    const size_t smgl = 9216 * 3 + 17408;   // no W1nh
    const size_t smf  = (size_t)(4096 + 128 * 66 + 128) * sizeof(float);
    cudaFuncSetAttribute(k_pre_hist,    cudaFuncAttributeMaxDynamicSharedMemorySize, (int)smp);
    cudaFuncSetAttribute(k_gemm<false>, cudaFuncAttributeMaxDynamicSharedMemorySize, (int)smg);
    cudaFuncSetAttribute(k_gemm<true>,  cudaFuncAttributeMaxDynamicSharedMemorySize, (int)smgl);
    cudaFuncSetAttribute(k_final,       cudaFuncAttributeMaxDynamicSharedMemorySize, (int)smf);

    // launch 0: dense pre-GEMM (fp16 y out) + histograms (+ pad zeroing)
    k_pre_hist<<<592, 256, smp>>>(x, W1f, ei, batch, yp, tp);
    // launch 1-2: CSR
    k_scanlb<<<NB, 1024>>>();
    k_fill<<<(NE + 255) / 256, 256>>>(ei);

    // per layer: gather (y->t fp16), then tensor-core gemm (t -> pool + y_next fp16)
    // launch 3 (profiled slot): gather layer 0
    k_gather<<<888, 256>>>(yp, b1f, tp);
    k_gemm<false><<<592, 256, smg>>>(tp, W2f, b2f, W1r, batch, yp, 0);
    k_gather<<<888, 256>>>(yp, b1r, tp);
    k_gemm<false><<<592, 256, smg>>>(tp, W2r, b2r, W1r + 4096, batch, yp, 64);
    k_gather<<<888, 256>>>(yp, b1r + 64, tp);
    k_gemm<false><<<592, 256, smg>>>(tp, W2r + 4096, b2r + 64, W1r + 2 * 4096, batch, yp, 128);
    k_gather<<<888, 256>>>(yp, b1r + 128, tp);
    k_gemm<true><<<592, 256, smgl>>>(tp, W2r + 2 * 4096, b2r + 128, nullptr, batch, nullptr, 192);

    // graph-granularity tail
    k_jk<<<NG, 64>>>(Wjk, bjk);
    k_final<<<1, 128, smf>>>(Wc1, bc1, gamma, beta, Wc2, bc2, out);

    // zero accumulators for the NEXT call (after all readers above)
    k_zero_post<<<256, 256>>>();
}